// round 2
// baseline (speedup 1.0000x reference)
#include <cuda_runtime.h>

#define B_    4096
#define F_    100
#define TPB   128
#define NPAIR 4950

typedef unsigned long long ull;

// Packed fp32x2 math (sm_10x: 2x fp32 FMA throughput vs 3-reg FFMA)
static __device__ __forceinline__ ull fma2(ull a, ull b, ull c) {
    ull d; asm("fma.rn.f32x2 %0, %1, %2, %3;" : "=l"(d) : "l"(a), "l"(b), "l"(c)); return d;
}
static __device__ __forceinline__ ull mul2(ull a, ull b) {
    ull d; asm("mul.rn.f32x2 %0, %1, %2;" : "=l"(d) : "l"(a), "l"(b)); return d;
}
static __device__ __forceinline__ float2 u2f(ull r) {
    float2 v; asm("mov.b64 {%0,%1}, %2;" : "=f"(v.x), "=f"(v.y) : "l"(r)); return v;
}

// Shared memory layout (floats):
//   Xs   [50][68]   X half-tile (two passes)      0    .. 3400
//   Wt   [32][64]   slots 0-15 wq*0.25, 16-31 wk  3400 .. 5448
//   wvc  [64]       wv column 0                   5448 .. 5512
//   Qs   [100][16]                                5512 .. 7112
//   Kv   [100][20]  k0..k15, v@16, pad            7112 .. 9112
//   z0s  [100]                                    9112 .. 9212
//   xc0  [100]                                    9212 .. 9312
#define SMEM_FLOATS 9312   // 37248 B -> 6 CTAs/SM

__global__ void __launch_bounds__(TPB, 6) dcap_kernel(
    const float* __restrict__ x,  const float* __restrict__ wq,
    const float* __restrict__ wk, const float* __restrict__ wv,
    float* __restrict__ out)
{
    extern __shared__ float sm[];
    float* Xs  = sm;
    float* Wt  = sm + 3400;
    float* wvc = sm + 5448;
    float* Qs  = sm + 5512;
    float* Kv  = sm + 7112;
    float* z0s = sm + 9112;
    float* xc0 = sm + 9212;

    const int t = threadIdx.x;
    const int b = blockIdx.x;

    // ---- Weights once: Wt[slot][d]; 0..15 = wq col (pre-scaled 0.25), 16..31 = wk col
    for (int i = t; i < 2048; i += TPB) {
        int s = i >> 6, d = i & 63;
        Wt[s * 64 + d] = (s < 16) ? wq[d * 64 + s] * 0.25f : wk[d * 64 + (s - 16)];
    }
    if (t < 64) wvc[t] = wv[t * 64];

    const float4* gx = (const float4*)(x + (size_t)b * (F_ * 64));

    // ---- Two passes of 50 rows: stage X half-tile, project Q/K/v ----
    #pragma unroll 1
    for (int p = 0; p < 2; p++) {
        const int base = p * 50;
        __syncthreads();                       // Xs free (and weights visible on p==0)
        for (int i = t; i < 50 * 16; i += TPB) {
            int f = i >> 4, c = i & 15;
            float4 v4 = __ldcs(&gx[(base + f) * 16 + c]);
            *(float4*)(Xs + f * 68 + c * 4) = v4;
        }
        __syncthreads();

        if (t < 50) xc0[base + t] = Xs[t * 68];

        // projection: 100 items = 25 row-pairs x 4 slot-groups
        if (t < 100) {
            const int fp = t % 25, grp = t / 25;
            const int f0 = fp * 2;
            const ulonglong2* xr0 = (const ulonglong2*)(Xs + f0 * 68);
            const ulonglong2* xr1 = (const ulonglong2*)(Xs + (f0 + 1) * 68);
            const ulonglong2* wr  = (const ulonglong2*)(Wt + grp * 8 * 64);
            ull a0[8], a1[8];
            #pragma unroll
            for (int k = 0; k < 8; k++) { a0[k] = 0ull; a1[k] = 0ull; }
            #pragma unroll 4
            for (int d4 = 0; d4 < 16; d4++) {
                ulonglong2 xv0 = xr0[d4], xv1 = xr1[d4];
                #pragma unroll
                for (int k = 0; k < 8; k++) {
                    ulonglong2 w = wr[k * 16 + d4];   // broadcast across lanes in grp
                    a0[k] = fma2(xv0.x, w.x, a0[k]);
                    a0[k] = fma2(xv0.y, w.y, a0[k]);
                    a1[k] = fma2(xv1.x, w.x, a1[k]);
                    a1[k] = fma2(xv1.y, w.y, a1[k]);
                }
            }
            const int r0 = base + f0, r1 = r0 + 1;
            #pragma unroll
            for (int k = 0; k < 8; k++) {
                float2 v0 = u2f(a0[k]), v1 = u2f(a1[k]);
                float s0 = v0.x + v0.y, s1 = v1.x + v1.y;
                int slot = grp * 8 + k;
                if (slot < 16) { Qs[r0 * 16 + slot] = s0; Qs[r1 * 16 + slot] = s1; }
                else           { Kv[r0 * 20 + slot - 16] = s0; Kv[r1 * 20 + slot - 16] = s1; }
            }
        }
        // v column (head0/hid0 of x@wv)
        if (t < 50) {
            const ulonglong2* xr = (const ulonglong2*)(Xs + t * 68);
            const ulonglong2* wr = (const ulonglong2*)wvc;
            ull acc0 = 0ull, acc1 = 0ull;
            #pragma unroll
            for (int d4 = 0; d4 < 16; d4++) {
                ulonglong2 xv = xr[d4], w = wr[d4];
                acc0 = fma2(xv.x, w.x, acc0);
                acc1 = fma2(xv.y, w.y, acc1);
            }
            float2 va = u2f(acc0), vb = u2f(acc1);
            Kv[(base + t) * 20 + 16] = (va.x + vb.x) + (va.y + vb.y);
        }
    }
    __syncthreads();

    // ---- Attention, row per thread; scores O(1) so no max-subtraction needed.
    //      Unroll x2 with independent accumulator pairs for ILP.
    if (t < F_) {
        const ulonglong2* qr = (const ulonglong2*)(Qs + t * 16);
        ulonglong2 q01 = qr[0], q23 = qr[1], q45 = qr[2], q67 = qr[3];
        float den0 = 0.f, den1 = 0.f, za0 = 0.f, za1 = 0.f;
        #pragma unroll 2
        for (int g = 0; g < F_; g += 2) {
            const ulonglong2* kr0 = (const ulonglong2*)(Kv + g * 20);
            const ulonglong2* kr1 = (const ulonglong2*)(Kv + g * 20 + 20);
            ulonglong2 ka = kr0[0], kb = kr0[1], kc = kr0[2], kd = kr0[3];
            ull e0 = mul2(q01.x, ka.x);
            ull e1 = mul2(q01.y, ka.y);
            e0 = fma2(q23.x, kb.x, e0);
            e1 = fma2(q23.y, kb.y, e1);
            e0 = fma2(q45.x, kc.x, e0);
            e1 = fma2(q45.y, kc.y, e1);
            e0 = fma2(q67.x, kd.x, e0);
            e1 = fma2(q67.y, kd.y, e1);
            ulonglong2 la = kr1[0], lb = kr1[1], lc = kr1[2], ld = kr1[3];
            ull f0 = mul2(q01.x, la.x);
            ull f1 = mul2(q01.y, la.y);
            f0 = fma2(q23.x, lb.x, f0);
            f1 = fma2(q23.y, lb.y, f1);
            f0 = fma2(q45.x, lc.x, f0);
            f1 = fma2(q45.y, lc.y, f1);
            f0 = fma2(q67.x, ld.x, f0);
            f1 = fma2(q67.y, ld.y, f1);
            float2 ea = u2f(e0), eb = u2f(e1);
            float2 fa = u2f(f0), fb = u2f(f1);
            float s0 = (ea.x + eb.x) + (ea.y + eb.y);
            float s1 = (fa.x + fb.x) + (fa.y + fb.y);
            float v0 = Kv[g * 20 + 16];
            float v1 = Kv[g * 20 + 36];
            float ex0 = __expf(s0);
            float ex1 = __expf(s1);
            den0 += ex0; za0 = fmaf(ex0, v0, za0);
            den1 += ex1; za1 = fmaf(ex1, v1, za1);
        }
        z0s[t] = (za0 + za1) / (den0 + den1);
    }
    __syncthreads();

    // ---- Pairwise output: p[pair(i,j)] = z0[i]*x[j,0]; per-thread early exit.
    float* ob = out + (size_t)b * NPAIR;
    const int imax = 99 - t;                    // thread t covers j = i+1+t for i < 99-t
    #pragma unroll 1
    for (int i = 0; i < imax; i++) {
        int rowoff = i * (199 - i) / 2;
        __stcs(ob + rowoff + t, z0s[i] * xc0[i + 1 + t]);
    }
}

extern "C" void kernel_launch(void* const* d_in, const int* in_sizes, int n_in,
                              void* d_out, int out_size)
{
    const float* x  = (const float*)d_in[0];
    const float* wq = (const float*)d_in[1];
    const float* wk = (const float*)d_in[2];
    const float* wv = (const float*)d_in[3];
    float* out = (float*)d_out;
    (void)in_sizes; (void)n_in; (void)out_size;

    const int smem_bytes = SMEM_FLOATS * (int)sizeof(float);
    cudaFuncSetAttribute(dcap_kernel, cudaFuncAttributeMaxDynamicSharedMemorySize, smem_bytes);
    dcap_kernel<<<B_, TPB, smem_bytes>>>(x, wq, wk, wv, out);
}

// round 3
// speedup vs baseline: 1.1792x; 1.1792x over previous
#include <cuda_runtime.h>

#define B_    4096
#define F_    100
#define TPB   128
#define NPAIR 4950

typedef unsigned long long ull;

static __device__ __forceinline__ ull fma2(ull a, ull b, ull c) {
    ull d; asm("fma.rn.f32x2 %0, %1, %2, %3;" : "=l"(d) : "l"(a), "l"(b), "l"(c)); return d;
}
static __device__ __forceinline__ ull mul2(ull a, ull b) {
    ull d; asm("mul.rn.f32x2 %0, %1, %2;" : "=l"(d) : "l"(a), "l"(b)); return d;
}
static __device__ __forceinline__ float2 u2f(ull r) {
    float2 v; asm("mov.b64 {%0,%1}, %2;" : "=f"(v.x), "=f"(v.y) : "l"(r)); return v;
}

// dot of 16 floats given as 8 packed f32x2 ulls; two independent chains for ILP
static __device__ __forceinline__ float dot16(const ull* q, const ull* k) {
    ull a = mul2(q[0], k[0]);
    ull b = mul2(q[1], k[1]);
    a = fma2(q[2], k[2], a);
    b = fma2(q[3], k[3], b);
    a = fma2(q[4], k[4], a);
    b = fma2(q[5], k[5], b);
    a = fma2(q[6], k[6], a);
    b = fma2(q[7], k[7], b);
    float2 fa = u2f(a), fb = u2f(b);
    return (fa.x + fb.x) + (fa.y + fb.y);
}

// Shared memory layout (floats):
//   Xs   [100][64]  swizzled X (float4 block c of row f stored at ((c + (f>>2)) & 15))
//   Wt   [33][64]   slot-major: 0-15 wq*0.25, 16-31 wk, 32 wv-col0
//   Qs   [100][20]  q slots 0..15 (stride 20 to spread store banks)
//   Kv   [100][20]  k slots 0..15
//   Vp   [100]      v column
//   z0s  [100], xc0 [100], part [100][4] partial (den0,za0,den1,za1)
#define OFF_X   0
#define OFF_W   6400
#define OFF_Q   8512
#define OFF_K   10512
#define OFF_V   12512
#define OFF_Z   12612
#define OFF_X0  12712
#define OFF_P   12812
#define SMEM_FLOATS 13212   // 52848 bytes -> 4 CTAs/SM

__global__ void __launch_bounds__(TPB, 4) dcap_kernel(
    const float* __restrict__ x,  const float* __restrict__ wq,
    const float* __restrict__ wk, const float* __restrict__ wv,
    float* __restrict__ out)
{
    extern __shared__ float sm[];
    float* Xs  = sm + OFF_X;
    float* Wt  = sm + OFF_W;
    float* Qs  = sm + OFF_Q;
    float* Kv  = sm + OFF_K;
    float* Vp  = sm + OFF_V;
    float* z0s = sm + OFF_Z;
    float* xc0 = sm + OFF_X0;
    float* part= sm + OFF_P;

    const int t = threadIdx.x;
    const int b = blockIdx.x;

    // ---- Weights: slot-major rows of 64 (wq pre-scaled by 1/sqrt(16)) ----
    for (int i = t; i < 33 * 64; i += TPB) {
        int s = i >> 6, d = i & 63;
        Wt[i] = (s < 16) ? wq[d * 64 + s] * 0.25f
                         : (s < 32 ? wk[d * 64 + (s - 16)] : wv[d * 64]);
    }
    // ---- X tile, rotation-swizzled per row: block c -> ((c + (f>>2)) & 15) ----
    const float4* gx = (const float4*)(x + (size_t)b * (F_ * 64));
    for (int i = t; i < F_ * 16; i += TPB) {
        int f = i >> 4, c = i & 15;
        int blk = (c + (f >> 2)) & 15;
        *(float4*)(Xs + f * 64 + (blk << 2)) = __ldcs(&gx[i]);
    }
    __syncthreads();

    if (t < F_) xc0[t] = Xs[t * 64 + ((((t >> 2)) & 15) << 2)];   // x[t][0]

    // ================= Projection: 4 rows x 8 slots per thread =================
    if (t < 100) {
        const int rp  = t % 25;           // row quad: rows 4rp..4rp+3
        const int grp = t / 25;           // slot group: slots 8*grp..+7
        const ulonglong2* wbase = (const ulonglong2*)(Wt + grp * 8 * 64);

        ull acc[4][8];                     // [row j][slot k], packs (even-d, odd-d) partials
        #pragma unroll
        for (int j = 0; j < 4; j++)
            #pragma unroll
            for (int k = 0; k < 8; k++) acc[j][k] = 0ull;

        #pragma unroll
        for (int d4 = 0; d4 < 16; d4++) {
            int blk = ((d4 + rp) & 15) << 2;
            ulonglong2 xv[4];
            #pragma unroll
            for (int j = 0; j < 4; j++)
                xv[j] = *(const ulonglong2*)(Xs + (4 * rp + j) * 64 + blk);
            #pragma unroll
            for (int k = 0; k < 8; k++) {
                ulonglong2 w = wbase[k * 16 + d4];
                #pragma unroll
                for (int j = 0; j < 4; j++) {
                    acc[j][k] = fma2(xv[j].x, w.x, acc[j][k]);
                    acc[j][k] = fma2(xv[j].y, w.y, acc[j][k]);
                }
            }
        }
        float* dstp = (grp < 2) ? Qs : Kv;
        const int colb = (grp & 1) * 8;
        #pragma unroll
        for (int j = 0; j < 4; j++) {
            int f = 4 * rp + j;
            #pragma unroll
            for (int k2 = 0; k2 < 4; k2++) {
                float2 a = u2f(acc[j][2 * k2]);
                float2 c = u2f(acc[j][2 * k2 + 1]);
                float2 st = make_float2(a.x + a.y, c.x + c.y);
                *(float2*)(dstp + f * 20 + colb + 2 * k2) = st;
            }
        }
    }
    // ---- v column ----
    if (t < 100) {
        const ulonglong2* wv2 = (const ulonglong2*)(Wt + 32 * 64);
        const int rot = (t >> 2) & 15;
        ull a = 0ull, c = 0ull;
        #pragma unroll
        for (int d4 = 0; d4 < 16; d4++) {
            ulonglong2 xv = *(const ulonglong2*)(Xs + t * 64 + (((d4 + rot) & 15) << 2));
            ulonglong2 w  = wv2[d4];
            a = fma2(xv.x, w.x, a);
            c = fma2(xv.y, w.y, c);
        }
        float2 fa = u2f(a), fc = u2f(c);
        Vp[t] = (fa.x + fc.x) + (fa.y + fc.y);
    }
    __syncthreads();

    // ============ Attention: thread = (row-pair, g-half); warp-uniform g ============
    // warp0: pr 0-31 h0 | warp1: pr 0-31 h1 | warp2: pr 32-49 h0 | warp3: pr 32-49 h1
    {
        const int half = (t >> 5) & 1;
        const int pr   = (t & 31) | ((t >> 6) << 5);
        if (pr < 50) {
            const int r0 = 2 * pr;
            ull q[2][8];
            #pragma unroll
            for (int r = 0; r < 2; r++) {
                const ulonglong2* qp = (const ulonglong2*)(Qs + (r0 + r) * 20);
                #pragma unroll
                for (int m = 0; m < 4; m++) {
                    ulonglong2 v = qp[m];
                    q[r][2 * m] = v.x; q[r][2 * m + 1] = v.y;
                }
            }
            float den0 = 0.f, den1 = 0.f, za0 = 0.f, za1 = 0.f;
            const int gb = half * 50;
            #pragma unroll 2
            for (int gi = 0; gi < 50; gi += 2) {
                const int g = gb + gi;
                ull k0[8], k1[8];
                const ulonglong2* kp0 = (const ulonglong2*)(Kv + g * 20);
                const ulonglong2* kp1 = (const ulonglong2*)(Kv + (g + 1) * 20);
                #pragma unroll
                for (int m = 0; m < 4; m++) {
                    ulonglong2 va = kp0[m]; k0[2 * m] = va.x; k0[2 * m + 1] = va.y;
                    ulonglong2 vb = kp1[m]; k1[2 * m] = vb.x; k1[2 * m + 1] = vb.y;
                }
                float2 vv = *(const float2*)(Vp + g);
                // scores are O(1..10): fp32 exp cannot overflow; skip max-subtract
                float s00 = dot16(q[0], k0);
                float s01 = dot16(q[0], k1);
                float s10 = dot16(q[1], k0);
                float s11 = dot16(q[1], k1);
                float e00 = __expf(s00), e01 = __expf(s01);
                float e10 = __expf(s10), e11 = __expf(s11);
                den0 += e00 + e01;
                den1 += e10 + e11;
                za0 = fmaf(e00, vv.x, fmaf(e01, vv.y, za0));
                za1 = fmaf(e10, vv.x, fmaf(e11, vv.y, za1));
            }
            *(float4*)(part + (half * 50 + pr) * 4) = make_float4(den0, za0, den1, za1);
        }
    }
    __syncthreads();
    if (t < 50) {
        float4 p0 = *(const float4*)(part + t * 4);
        float4 p1 = *(const float4*)(part + (50 + t) * 4);
        z0s[2 * t]     = (p0.y + p1.y) / (p0.x + p1.x);
        z0s[2 * t + 1] = (p0.w + p1.w) / (p0.z + p1.z);
    }
    __syncthreads();

    // ---- Pairwise output: p[pair(i,j)] = z0[i]*x[j,0]; per-thread early exit ----
    float* ob = out + (size_t)b * NPAIR;
    const int imax = 99 - t;
    #pragma unroll 1
    for (int i = 0; i < imax; i++) {
        int rowoff = i * (199 - i) / 2;
        __stcs(ob + rowoff + t, z0s[i] * xc0[i + 1 + t]);
    }
}

extern "C" void kernel_launch(void* const* d_in, const int* in_sizes, int n_in,
                              void* d_out, int out_size)
{
    const float* x  = (const float*)d_in[0];
    const float* wq = (const float*)d_in[1];
    const float* wk = (const float*)d_in[2];
    const float* wv = (const float*)d_in[3];
    float* out = (float*)d_out;
    (void)in_sizes; (void)n_in; (void)out_size;

    const int smem_bytes = SMEM_FLOATS * (int)sizeof(float);
    cudaFuncSetAttribute(dcap_kernel, cudaFuncAttributeMaxDynamicSharedMemorySize, smem_bytes);
    dcap_kernel<<<B_, TPB, smem_bytes>>>(x, wq, wk, wv, out);
}